// round 11
// baseline (speedup 1.0000x reference)
#include <cuda_runtime.h>
#include <cuda_bf16.h>
#include <math.h>

#define NB 64
#define N 1024
#define ITERS 10

// Scratch (allocation-free, static device memory)
__device__ __align__(16) float g_u[NB * N];     // u1, later u10
__device__ __align__(16) float g_v[NB * N];     // log-domain col potential
__device__ __align__(16) float g_r[NB * N];     // exp-domain row scaling
__device__ __align__(16) float g_c[NB * N];     // exp-domain col scaling
// K = exp(A - u1) stored as bf16
__device__ __align__(16) unsigned short g_q[(size_t)NB * N * N];

__device__ __forceinline__ float clampA(float m) {
    return fminf(fmaxf(m, -25.0f), 25.0f) * 10.0f;
}
__device__ __forceinline__ float blo(unsigned int w) { return __uint_as_float(w << 16); }
__device__ __forceinline__ float bhi(unsigned int w) { return __uint_as_float(w & 0xFFFF0000u); }
__device__ __forceinline__ unsigned int packbf(float lo, float hi) {
    __nv_bfloat162 h = __floats2bfloat162_rn(lo, hi);
    return *reinterpret_cast<unsigned int*>(&h);
}

// ---------------------------------------------------------------------------
// Pass 0: exact row-LSE (u1) + K = exp(A - u1) in bf16. Also r = 1.
// ---------------------------------------------------------------------------
__global__ void __launch_bounds__(256, 2) exp_quant_kernel(const float* __restrict__ M) {
    int rl   = threadIdx.x >> 6;
    int tr   = threadIdx.x & 63;
    int half = tr >> 5;
    int lane = tr & 31;
    size_t r = (size_t)blockIdx.x * 4 + rl;

    const float4* __restrict__ row4 = reinterpret_cast<const float4*>(M) + r * (N / 4);

    float x[16];
    float mx = -1e30f;
#pragma unroll
    for (int k = 0; k < 4; k++) {
        int idx = (k & 1) + 2 * tr + (k >> 1) * 128;
        float4 a = row4[idx];
        float x0 = clampA(a.x), x1 = clampA(a.y), x2 = clampA(a.z), x3 = clampA(a.w);
        x[4 * k + 0] = x0; x[4 * k + 1] = x1; x[4 * k + 2] = x2; x[4 * k + 3] = x3;
        mx = fmaxf(mx, fmaxf(fmaxf(x0, x1), fmaxf(x2, x3)));
    }
#pragma unroll
    for (int o = 16; o > 0; o >>= 1)
        mx = fmaxf(mx, __shfl_xor_sync(0xFFFFFFFFu, mx, o));

    __shared__ float rm[4][2], rs[4][2];
    if (lane == 0) rm[rl][half] = mx;
    __syncthreads();
    mx = fmaxf(rm[rl][0], rm[rl][1]);

    float s = 0.0f;
#pragma unroll
    for (int k = 0; k < 16; k++) {
        x[k] = __expf(x[k] - mx);
        s += x[k];
    }
#pragma unroll
    for (int o = 16; o > 0; o >>= 1)
        s += __shfl_xor_sync(0xFFFFFFFFu, s, o);
    if (lane == 0) rs[rl][half] = s;
    __syncthreads();
    float S = rs[rl][0] + rs[rl][1];
    float inv = 1.0f / S;

    uint4 w;
    uint4* __restrict__ q4 = reinterpret_cast<uint4*>(g_q) + r * 128;
    w.x = packbf(x[0] * inv, x[1] * inv);
    w.y = packbf(x[2] * inv, x[3] * inv);
    w.z = packbf(x[4] * inv, x[5] * inv);
    w.w = packbf(x[6] * inv, x[7] * inv);
    q4[tr] = w;
    w.x = packbf(x[8] * inv, x[9] * inv);
    w.y = packbf(x[10] * inv, x[11] * inv);
    w.z = packbf(x[12] * inv, x[13] * inv);
    w.w = packbf(x[14] * inv, x[15] * inv);
    q4[64 + tr] = w;

    if (tr == 0) {
        g_u[r] = mx + __logf(S);
        g_r[r] = 1.0f;
    }
}

// ---------------------------------------------------------------------------
// Full-column col pass: S_j = Sum_i K_ij * r_i over ALL 1024 rows, then
// writes c_j = 1/S_j and v_j = log S_j directly (no partials, no combine).
// Tile = 256 bf16 cols x 1024 rows. Block (32,8) = 256 threads:
// tx = uint4 col-word (8 bf16 cols), ty = row group (rows ty+8k, k<128).
// Grid (4, NB). Batches processed DESCENDING (L2 ping-pong with row pass).
// ---------------------------------------------------------------------------
__global__ void __launch_bounds__(256) col_sum_kernel() {
    int b  = NB - 1 - (int)blockIdx.y;
    int tx = threadIdx.x;           // 0..31
    int ty = threadIdx.y;           // 0..7
    int c  = blockIdx.x * 32 + tx;  // uint4 index within row [0,128)

    __shared__ float sr[N];
    __shared__ float red[8][256];

    int t = ty * 32 + tx;
    for (int k = t; k < N; k += 256)
        sr[k] = g_r[b * N + k];
    __syncthreads();

    const uint4* __restrict__ q4 = reinterpret_cast<const uint4*>(g_q)
                                   + (size_t)b * N * 128 + c;

    float acc[8] = {0.f, 0.f, 0.f, 0.f, 0.f, 0.f, 0.f, 0.f};
#pragma unroll 8
    for (int k = 0; k < 128; k++) {
        int i = ty + 8 * k;
        uint4 q = q4[(size_t)i * 128];
        float rr = sr[i];
        acc[0] += blo(q.x) * rr; acc[1] += bhi(q.x) * rr;
        acc[2] += blo(q.y) * rr; acc[3] += bhi(q.y) * rr;
        acc[4] += blo(q.z) * rr; acc[5] += bhi(q.z) * rr;
        acc[6] += blo(q.w) * rr; acc[7] += bhi(q.w) * rr;
    }

    // red[ty][q*32+tx] = acc[q] — conflict-free writes and reads
#pragma unroll
    for (int q = 0; q < 8; q++)
        red[ty][q * 32 + tx] = acc[q];
    __syncthreads();

    float S = red[0][t];
#pragma unroll
    for (int k = 1; k < 8; k++)
        S += red[k][t];
    S = fmaxf(S, 1e-30f);

    // thread t holds local col (t&31)*8 + (t>>5)
    int j = blockIdx.x * 256 + (t & 31) * 8 + (t >> 5);
    g_c[b * N + j] = 1.0f / S;
    g_v[b * N + j] = __logf(S);
}

// ---------------------------------------------------------------------------
// Exp-domain row pass: S_i = Sum_j K_ij * c_j. c amortized over 4 rows/thread.
// Block 256 = 4 row-groups x 64 threads; block covers 16 rows (one batch).
//   write_u == 0:  r_i = 1/S_i            (iterations 2..9)
//   write_u == 1:  u10_i = u1_i + log S_i (iteration 10 row pass)
// Blocks ascend (L2 ping-pong: col pass ended at low addresses).
// ---------------------------------------------------------------------------
__global__ void __launch_bounds__(256) row_dot_kernel(int write_u) {
    int rg   = threadIdx.x >> 6;        // 0..3 row-group of 4 rows
    int tr   = threadIdx.x & 63;
    int half = tr >> 5;
    int lane = tr & 31;
    size_t rbase = (size_t)blockIdx.x * 16 + rg * 4;
    int b = (int)(rbase >> 10);

    const float4* __restrict__ c4 = reinterpret_cast<const float4*>(g_c + b * N);
    float4 ca0 = c4[2 * tr];
    float4 cb0 = c4[2 * tr + 1];
    float4 ca1 = c4[128 + 2 * tr];
    float4 cb1 = c4[129 + 2 * tr];

    float sum[4];
#pragma unroll
    for (int rr = 0; rr < 4; rr++) {
        const uint4* __restrict__ q4 = reinterpret_cast<const uint4*>(g_q) + (rbase + rr) * 128;
        uint4 qa = q4[tr];
        uint4 qb = q4[64 + tr];
        float s = 0.0f;
        s += blo(qa.x) * ca0.x + bhi(qa.x) * ca0.y;
        s += blo(qa.y) * ca0.z + bhi(qa.y) * ca0.w;
        s += blo(qa.z) * cb0.x + bhi(qa.z) * cb0.y;
        s += blo(qa.w) * cb0.z + bhi(qa.w) * cb0.w;
        s += blo(qb.x) * ca1.x + bhi(qb.x) * ca1.y;
        s += blo(qb.y) * ca1.z + bhi(qb.y) * ca1.w;
        s += blo(qb.z) * cb1.x + bhi(qb.z) * cb1.y;
        s += blo(qb.w) * cb1.z + bhi(qb.w) * cb1.w;
        sum[rr] = s;
    }
#pragma unroll
    for (int rr = 0; rr < 4; rr++) {
#pragma unroll
        for (int o = 16; o > 0; o >>= 1)
            sum[rr] += __shfl_xor_sync(0xFFFFFFFFu, sum[rr], o);
    }

    __shared__ float rs[4][4][2];
    if (lane == 0) {
#pragma unroll
        for (int rr = 0; rr < 4; rr++)
            rs[rg][rr][half] = sum[rr];
    }
    __syncthreads();

    if (threadIdx.x < 16) {
        int g = threadIdx.x >> 2, rr = threadIdx.x & 3;
        size_t r = (size_t)blockIdx.x * 16 + g * 4 + rr;
        float S = fmaxf(rs[g][rr][0] + rs[g][rr][1], 1e-30f);
        if (write_u)
            g_u[r] = g_u[r] + __logf(S);
        else
            g_r[r] = 1.0f / S;
    }
}

// ---------------------------------------------------------------------------
// EXACT last col pass fused with output write (iteration 10 col + exp).
// float4 layout: thread (tx,ty) = float4-col tx (of 8), rows ty+128k (k<8).
// Block 1024 = tile 32 cols x 1024 rows. Grid (32, NB).
// ---------------------------------------------------------------------------
__global__ void __launch_bounds__(1024) col_lse_finalize_kernel(const float* __restrict__ M,
                                                                float* __restrict__ out) {
    int b  = blockIdx.y;
    int tx = threadIdx.x & 7;       // float4-col within tile
    int ty = threadIdx.x >> 3;      // 0..127 row group
    int lane = threadIdx.x & 31;
    int wid  = threadIdx.x >> 5;    // 0..31
    int j4 = blockIdx.x * 8 + tx;   // global float4-col

    __shared__ float us[N];
    __shared__ float4 redm[32][8];
    __shared__ float4 reds[32][8];

    us[threadIdx.x] = g_u[b * N + threadIdx.x];
    __syncthreads();

    const float4* __restrict__ base = reinterpret_cast<const float4*>(M)
                                      + (size_t)b * N * (N / 4) + j4;

    float4 xv[8];
    float4 mx = make_float4(-1e30f, -1e30f, -1e30f, -1e30f);
#pragma unroll
    for (int k = 0; k < 8; k++) {
        int i = ty + 128 * k;
        float4 a = base[(size_t)i * (N / 4)];
        float u = us[i];
        float4 t;
        t.x = clampA(a.x) - u; t.y = clampA(a.y) - u;
        t.z = clampA(a.z) - u; t.w = clampA(a.w) - u;
        xv[k] = t;
        mx.x = fmaxf(mx.x, t.x); mx.y = fmaxf(mx.y, t.y);
        mx.z = fmaxf(mx.z, t.z); mx.w = fmaxf(mx.w, t.w);
    }

    // warp pre-reduce over the 4 row-lanes (offsets 8, 16 preserve tx = lane&7)
#pragma unroll
    for (int o = 8; o <= 16; o <<= 1) {
        mx.x = fmaxf(mx.x, __shfl_xor_sync(0xFFFFFFFFu, mx.x, o));
        mx.y = fmaxf(mx.y, __shfl_xor_sync(0xFFFFFFFFu, mx.y, o));
        mx.z = fmaxf(mx.z, __shfl_xor_sync(0xFFFFFFFFu, mx.z, o));
        mx.w = fmaxf(mx.w, __shfl_xor_sync(0xFFFFFFFFu, mx.w, o));
    }
    if (lane < 8) redm[wid][lane] = mx;
    __syncthreads();
#pragma unroll
    for (int h = 16; h > 0; h >>= 1) {
        if (threadIdx.x < (unsigned)(h * 8)) {
            int w = threadIdx.x >> 3, x = threadIdx.x & 7;
            float4 a = redm[w][x], c = redm[w + h][x];
            a.x = fmaxf(a.x, c.x); a.y = fmaxf(a.y, c.y);
            a.z = fmaxf(a.z, c.z); a.w = fmaxf(a.w, c.w);
            redm[w][x] = a;
        }
        __syncthreads();
    }
    float4 MX = redm[0][tx];

    float4 s = make_float4(0.f, 0.f, 0.f, 0.f);
#pragma unroll
    for (int k = 0; k < 8; k++) {
        s.x += __expf(xv[k].x - MX.x);
        s.y += __expf(xv[k].y - MX.y);
        s.z += __expf(xv[k].z - MX.z);
        s.w += __expf(xv[k].w - MX.w);
    }
#pragma unroll
    for (int o = 8; o <= 16; o <<= 1) {
        s.x += __shfl_xor_sync(0xFFFFFFFFu, s.x, o);
        s.y += __shfl_xor_sync(0xFFFFFFFFu, s.y, o);
        s.z += __shfl_xor_sync(0xFFFFFFFFu, s.z, o);
        s.w += __shfl_xor_sync(0xFFFFFFFFu, s.w, o);
    }
    if (lane < 8) reds[wid][lane] = s;
    __syncthreads();
#pragma unroll
    for (int h = 16; h > 0; h >>= 1) {
        if (threadIdx.x < (unsigned)(h * 8)) {
            int w = threadIdx.x >> 3, x = threadIdx.x & 7;
            float4 a = reds[w][x], c = reds[w + h][x];
            a.x += c.x; a.y += c.y; a.z += c.z; a.w += c.w;
            reds[w][x] = a;
        }
        __syncthreads();
    }
    float4 SS = reds[0][tx];

    float4 V;
    V.x = MX.x + __logf(SS.x);
    V.y = MX.y + __logf(SS.y);
    V.z = MX.z + __logf(SS.z);
    V.w = MX.w + __logf(SS.w);

    float4* __restrict__ obase = reinterpret_cast<float4*>(out)
                                 + (size_t)b * N * (N / 4) + j4;
#pragma unroll
    for (int k = 0; k < 8; k++) {
        int i = ty + 128 * k;
        float4 o;
        o.x = __expf(xv[k].x - V.x);
        o.y = __expf(xv[k].y - V.y);
        o.z = __expf(xv[k].z - V.z);
        o.w = __expf(xv[k].w - V.w);
        obase[(size_t)i * (N / 4)] = o;
    }
}

extern "C" void kernel_launch(void* const* d_in, const int* in_sizes, int n_in,
                              void* d_out, int out_size) {
    const float* M = (const float*)d_in[0];
    float* out = (float*)d_out;

    exp_quant_kernel<<<(NB * N) / 4, 256>>>(M);

    for (int it = 0; it < ITERS - 1; it++) {
        col_sum_kernel<<<dim3(4, NB), dim3(32, 8)>>>();
        row_dot_kernel<<<(NB * N) / 16, 256>>>(it == ITERS - 2 ? 1 : 0);
    }

    col_lse_finalize_kernel<<<dim3(N / 32, NB), 1024>>>(M, out);
}

// round 12
// speedup vs baseline: 1.3374x; 1.3374x over previous
#include <cuda_runtime.h>
#include <cuda_bf16.h>
#include <math.h>

#define NB 64
#define N 1024
#define ITERS 10

// Scratch (allocation-free, static device memory)
__device__ __align__(16) float g_u[NB * N];     // u1, later u10
__device__ __align__(16) float g_v[NB * N];     // log-domain col potential
__device__ __align__(16) float g_r[NB * N];     // exp-domain row scaling
__device__ __align__(16) float g_c[NB * N];     // exp-domain col scaling
// K = exp(A - u1) stored as bf16
__device__ __align__(16) unsigned short g_q[(size_t)NB * N * N];

__device__ __forceinline__ float clampA(float m) {
    return fminf(fmaxf(m, -25.0f), 25.0f) * 10.0f;
}
__device__ __forceinline__ float blo(unsigned int w) { return __uint_as_float(w << 16); }
__device__ __forceinline__ float bhi(unsigned int w) { return __uint_as_float(w & 0xFFFF0000u); }
__device__ __forceinline__ unsigned int packbf(float lo, float hi) {
    __nv_bfloat162 h = __floats2bfloat162_rn(lo, hi);
    return *reinterpret_cast<unsigned int*>(&h);
}

// ---------------------------------------------------------------------------
// Pass 0: exact row-LSE (u1) + K = exp(A - u1) in bf16. Also r = 1.
// ---------------------------------------------------------------------------
__global__ void __launch_bounds__(256, 2) exp_quant_kernel(const float* __restrict__ M) {
    int rl   = threadIdx.x >> 6;
    int tr   = threadIdx.x & 63;
    int half = tr >> 5;
    int lane = tr & 31;
    size_t r = (size_t)blockIdx.x * 4 + rl;

    const float4* __restrict__ row4 = reinterpret_cast<const float4*>(M) + r * (N / 4);

    float x[16];
    float mx = -1e30f;
#pragma unroll
    for (int k = 0; k < 4; k++) {
        int idx = (k & 1) + 2 * tr + (k >> 1) * 128;
        float4 a = row4[idx];
        float x0 = clampA(a.x), x1 = clampA(a.y), x2 = clampA(a.z), x3 = clampA(a.w);
        x[4 * k + 0] = x0; x[4 * k + 1] = x1; x[4 * k + 2] = x2; x[4 * k + 3] = x3;
        mx = fmaxf(mx, fmaxf(fmaxf(x0, x1), fmaxf(x2, x3)));
    }
#pragma unroll
    for (int o = 16; o > 0; o >>= 1)
        mx = fmaxf(mx, __shfl_xor_sync(0xFFFFFFFFu, mx, o));

    __shared__ float rm[4][2], rs[4][2];
    if (lane == 0) rm[rl][half] = mx;
    __syncthreads();
    mx = fmaxf(rm[rl][0], rm[rl][1]);

    float s = 0.0f;
#pragma unroll
    for (int k = 0; k < 16; k++) {
        x[k] = __expf(x[k] - mx);
        s += x[k];
    }
#pragma unroll
    for (int o = 16; o > 0; o >>= 1)
        s += __shfl_xor_sync(0xFFFFFFFFu, s, o);
    if (lane == 0) rs[rl][half] = s;
    __syncthreads();
    float S = rs[rl][0] + rs[rl][1];
    float inv = 1.0f / S;

    uint4 w;
    uint4* __restrict__ q4 = reinterpret_cast<uint4*>(g_q) + r * 128;
    w.x = packbf(x[0] * inv, x[1] * inv);
    w.y = packbf(x[2] * inv, x[3] * inv);
    w.z = packbf(x[4] * inv, x[5] * inv);
    w.w = packbf(x[6] * inv, x[7] * inv);
    q4[tr] = w;
    w.x = packbf(x[8] * inv, x[9] * inv);
    w.y = packbf(x[10] * inv, x[11] * inv);
    w.z = packbf(x[12] * inv, x[13] * inv);
    w.w = packbf(x[14] * inv, x[15] * inv);
    q4[64 + tr] = w;

    if (tr == 0) {
        g_u[r] = mx + __logf(S);
        g_r[r] = 1.0f;
    }
}

// ---------------------------------------------------------------------------
// Full-column col pass: S_j = Sum_i K_ij * r_i over ALL 1024 rows; writes
// c_j = 1/S_j and v_j = log S_j directly (no partials, no combine kernel).
// Tile = 64 bf16 cols x 1024 rows. Block 256 = (8 uint4 words x 32 row-groups):
// tx = word, ty = row group; thread covers rows ty+32k (k<32).
// Grid (16, NB) = 1024 blocks. Batches DESCENDING (L2 ping-pong with row pass).
// ---------------------------------------------------------------------------
__global__ void __launch_bounds__(256) col_sum_kernel() {
    int b  = NB - 1 - (int)blockIdx.y;
    int tx = threadIdx.x & 7;       // uint4 word within tile
    int ty = threadIdx.x >> 3;      // 0..31 row group
    int c  = blockIdx.x * 8 + tx;   // global uint4 word [0,128)

    __shared__ float sr[N];
    __shared__ float red[64][33];   // [local col][row group], padded

    for (int k = threadIdx.x; k < N; k += 256)
        sr[k] = g_r[b * N + k];
    __syncthreads();

    const uint4* __restrict__ q4 = reinterpret_cast<const uint4*>(g_q)
                                   + (size_t)b * N * 128 + c;

    float acc[8] = {0.f, 0.f, 0.f, 0.f, 0.f, 0.f, 0.f, 0.f};
#pragma unroll 8
    for (int k = 0; k < 32; k++) {
        int i = ty + 32 * k;
        uint4 q = q4[(size_t)i * 128];
        float rr = sr[i];
        acc[0] += blo(q.x) * rr; acc[1] += bhi(q.x) * rr;
        acc[2] += blo(q.y) * rr; acc[3] += bhi(q.y) * rr;
        acc[4] += blo(q.z) * rr; acc[5] += bhi(q.z) * rr;
        acc[6] += blo(q.w) * rr; acc[7] += bhi(q.w) * rr;
    }

    // transpose into shared: red[tx*8+q][ty]
#pragma unroll
    for (int q = 0; q < 8; q++)
        red[tx * 8 + q][ty] = acc[q];
    __syncthreads();

    // threads 0..63: one local column each; conflict-free row reads
    if (threadIdx.x < 64) {
        int l = threadIdx.x;
        float S = 0.0f;
#pragma unroll
        for (int k = 0; k < 32; k++)
            S += red[l][k];
        S = fmaxf(S, 1e-30f);
        int j = blockIdx.x * 64 + l;
        g_c[b * N + j] = 1.0f / S;
        g_v[b * N + j] = __logf(S);
    }
}

// ---------------------------------------------------------------------------
// Exp-domain row pass: S_i = Sum_j K_ij * c_j. c amortized over 4 rows/thread.
// Block 256 = 4 row-groups x 64 threads; block covers 16 rows (one batch).
//   write_u == 0:  r_i = 1/S_i            (iterations 2..9)
//   write_u == 1:  u10_i = u1_i + log S_i (iteration 10 row pass)
// Blocks ascend (L2 ping-pong: col pass ended at low addresses).
// ---------------------------------------------------------------------------
__global__ void __launch_bounds__(256) row_dot_kernel(int write_u) {
    int rg   = threadIdx.x >> 6;        // 0..3 row-group of 4 rows
    int tr   = threadIdx.x & 63;
    int half = tr >> 5;
    int lane = tr & 31;
    size_t rbase = (size_t)blockIdx.x * 16 + rg * 4;
    int b = (int)(rbase >> 10);

    const float4* __restrict__ c4 = reinterpret_cast<const float4*>(g_c + b * N);
    float4 ca0 = c4[2 * tr];
    float4 cb0 = c4[2 * tr + 1];
    float4 ca1 = c4[128 + 2 * tr];
    float4 cb1 = c4[129 + 2 * tr];

    float sum[4];
#pragma unroll
    for (int rr = 0; rr < 4; rr++) {
        const uint4* __restrict__ q4 = reinterpret_cast<const uint4*>(g_q) + (rbase + rr) * 128;
        uint4 qa = q4[tr];
        uint4 qb = q4[64 + tr];
        float s = 0.0f;
        s += blo(qa.x) * ca0.x + bhi(qa.x) * ca0.y;
        s += blo(qa.y) * ca0.z + bhi(qa.y) * ca0.w;
        s += blo(qa.z) * cb0.x + bhi(qa.z) * cb0.y;
        s += blo(qa.w) * cb0.z + bhi(qa.w) * cb0.w;
        s += blo(qb.x) * ca1.x + bhi(qb.x) * ca1.y;
        s += blo(qb.y) * ca1.z + bhi(qb.y) * ca1.w;
        s += blo(qb.z) * cb1.x + bhi(qb.z) * cb1.y;
        s += blo(qb.w) * cb1.z + bhi(qb.w) * cb1.w;
        sum[rr] = s;
    }
#pragma unroll
    for (int rr = 0; rr < 4; rr++) {
#pragma unroll
        for (int o = 16; o > 0; o >>= 1)
            sum[rr] += __shfl_xor_sync(0xFFFFFFFFu, sum[rr], o);
    }

    __shared__ float rs[4][4][2];
    if (lane == 0) {
#pragma unroll
        for (int rr = 0; rr < 4; rr++)
            rs[rg][rr][half] = sum[rr];
    }
    __syncthreads();

    if (threadIdx.x < 16) {
        int g = threadIdx.x >> 2, rr = threadIdx.x & 3;
        size_t r = (size_t)blockIdx.x * 16 + g * 4 + rr;
        float S = fmaxf(rs[g][rr][0] + rs[g][rr][1], 1e-30f);
        if (write_u)
            g_u[r] = g_u[r] + __logf(S);
        else
            g_r[r] = 1.0f / S;
    }
}

// ---------------------------------------------------------------------------
// EXACT last col pass fused with output write (iteration 10 col + exp).
// float4 layout: thread (tx,ty) = float4-col tx (of 8), rows ty+128k (k<8).
// Block 1024 = tile 32 cols x 1024 rows. Grid (32, NB).
// ---------------------------------------------------------------------------
__global__ void __launch_bounds__(1024) col_lse_finalize_kernel(const float* __restrict__ M,
                                                                float* __restrict__ out) {
    int b  = blockIdx.y;
    int tx = threadIdx.x & 7;       // float4-col within tile
    int ty = threadIdx.x >> 3;      // 0..127 row group
    int lane = threadIdx.x & 31;
    int wid  = threadIdx.x >> 5;    // 0..31
    int j4 = blockIdx.x * 8 + tx;   // global float4-col

    __shared__ float us[N];
    __shared__ float4 redm[32][8];
    __shared__ float4 reds[32][8];

    us[threadIdx.x] = g_u[b * N + threadIdx.x];
    __syncthreads();

    const float4* __restrict__ base = reinterpret_cast<const float4*>(M)
                                      + (size_t)b * N * (N / 4) + j4;

    float4 xv[8];
    float4 mx = make_float4(-1e30f, -1e30f, -1e30f, -1e30f);
#pragma unroll
    for (int k = 0; k < 8; k++) {
        int i = ty + 128 * k;
        float4 a = base[(size_t)i * (N / 4)];
        float u = us[i];
        float4 t;
        t.x = clampA(a.x) - u; t.y = clampA(a.y) - u;
        t.z = clampA(a.z) - u; t.w = clampA(a.w) - u;
        xv[k] = t;
        mx.x = fmaxf(mx.x, t.x); mx.y = fmaxf(mx.y, t.y);
        mx.z = fmaxf(mx.z, t.z); mx.w = fmaxf(mx.w, t.w);
    }

#pragma unroll
    for (int o = 8; o <= 16; o <<= 1) {
        mx.x = fmaxf(mx.x, __shfl_xor_sync(0xFFFFFFFFu, mx.x, o));
        mx.y = fmaxf(mx.y, __shfl_xor_sync(0xFFFFFFFFu, mx.y, o));
        mx.z = fmaxf(mx.z, __shfl_xor_sync(0xFFFFFFFFu, mx.z, o));
        mx.w = fmaxf(mx.w, __shfl_xor_sync(0xFFFFFFFFu, mx.w, o));
    }
    if (lane < 8) redm[wid][lane] = mx;
    __syncthreads();
#pragma unroll
    for (int h = 16; h > 0; h >>= 1) {
        if (threadIdx.x < (unsigned)(h * 8)) {
            int w = threadIdx.x >> 3, x = threadIdx.x & 7;
            float4 a = redm[w][x], c = redm[w + h][x];
            a.x = fmaxf(a.x, c.x); a.y = fmaxf(a.y, c.y);
            a.z = fmaxf(a.z, c.z); a.w = fmaxf(a.w, c.w);
            redm[w][x] = a;
        }
        __syncthreads();
    }
    float4 MX = redm[0][tx];

    float4 s = make_float4(0.f, 0.f, 0.f, 0.f);
#pragma unroll
    for (int k = 0; k < 8; k++) {
        s.x += __expf(xv[k].x - MX.x);
        s.y += __expf(xv[k].y - MX.y);
        s.z += __expf(xv[k].z - MX.z);
        s.w += __expf(xv[k].w - MX.w);
    }
#pragma unroll
    for (int o = 8; o <= 16; o <<= 1) {
        s.x += __shfl_xor_sync(0xFFFFFFFFu, s.x, o);
        s.y += __shfl_xor_sync(0xFFFFFFFFu, s.y, o);
        s.z += __shfl_xor_sync(0xFFFFFFFFu, s.z, o);
        s.w += __shfl_xor_sync(0xFFFFFFFFu, s.w, o);
    }
    if (lane < 8) reds[wid][lane] = s;
    __syncthreads();
#pragma unroll
    for (int h = 16; h > 0; h >>= 1) {
        if (threadIdx.x < (unsigned)(h * 8)) {
            int w = threadIdx.x >> 3, x = threadIdx.x & 7;
            float4 a = reds[w][x], c = reds[w + h][x];
            a.x += c.x; a.y += c.y; a.z += c.z; a.w += c.w;
            reds[w][x] = a;
        }
        __syncthreads();
    }
    float4 SS = reds[0][tx];

    float4 V;
    V.x = MX.x + __logf(SS.x);
    V.y = MX.y + __logf(SS.y);
    V.z = MX.z + __logf(SS.z);
    V.w = MX.w + __logf(SS.w);

    float4* __restrict__ obase = reinterpret_cast<float4*>(out)
                                 + (size_t)b * N * (N / 4) + j4;
#pragma unroll
    for (int k = 0; k < 8; k++) {
        int i = ty + 128 * k;
        float4 o;
        o.x = __expf(xv[k].x - V.x);
        o.y = __expf(xv[k].y - V.y);
        o.z = __expf(xv[k].z - V.z);
        o.w = __expf(xv[k].w - V.w);
        obase[(size_t)i * (N / 4)] = o;
    }
}

extern "C" void kernel_launch(void* const* d_in, const int* in_sizes, int n_in,
                              void* d_out, int out_size) {
    const float* M = (const float*)d_in[0];
    float* out = (float*)d_out;

    exp_quant_kernel<<<(NB * N) / 4, 256>>>(M);

    for (int it = 0; it < ITERS - 1; it++) {
        col_sum_kernel<<<dim3(16, NB), 256>>>();
        row_dot_kernel<<<(NB * N) / 16, 256>>>(it == ITERS - 2 ? 1 : 0);
    }

    col_lse_finalize_kernel<<<dim3(N / 32, NB), 1024>>>(M, out);
}

// round 13
// speedup vs baseline: 1.5240x; 1.1395x over previous
#include <cuda_runtime.h>
#include <cuda_bf16.h>
#include <math.h>

#define NB 64
#define N 1024
#define NPANEL 32              // row panels per batch (32 rows each)
#define PR 32                  // rows per panel

// Scratch (allocation-free, static device memory)
__device__ __align__(16) float g_u[NB * N];                 // u1, later u10
__device__ __align__(16) float g_c[NB * N];                 // exp-domain col scaling
__device__ __align__(16) float g_ps[NB * NPANEL * N];       // col partials (8 MB)
// K = exp(A - u1) stored as bf16
__device__ __align__(16) unsigned short g_q[(size_t)NB * N * N];

__device__ __forceinline__ float clampA(float m) {
    return fminf(fmaxf(m, -25.0f), 25.0f) * 10.0f;
}
__device__ __forceinline__ float blo(unsigned int w) { return __uint_as_float(w << 16); }
__device__ __forceinline__ float bhi(unsigned int w) { return __uint_as_float(w & 0xFFFF0000u); }
__device__ __forceinline__ unsigned int packbf(float lo, float hi) {
    __nv_bfloat162 h = __floats2bfloat162_rn(lo, hi);
    return *reinterpret_cast<unsigned int*>(&h);
}

// ---------------------------------------------------------------------------
// Pass 0: exact row-LSE (u1) + K = exp(A - u1) in bf16.
// ---------------------------------------------------------------------------
__global__ void __launch_bounds__(256, 2) exp_quant_kernel(const float* __restrict__ M) {
    int rl   = threadIdx.x >> 6;
    int tr   = threadIdx.x & 63;
    int half = tr >> 5;
    int lane = tr & 31;
    size_t r = (size_t)blockIdx.x * 4 + rl;

    const float4* __restrict__ row4 = reinterpret_cast<const float4*>(M) + r * (N / 4);

    float x[16];
    float mx = -1e30f;
#pragma unroll
    for (int k = 0; k < 4; k++) {
        int idx = (k & 1) + 2 * tr + (k >> 1) * 128;
        float4 a = row4[idx];
        float x0 = clampA(a.x), x1 = clampA(a.y), x2 = clampA(a.z), x3 = clampA(a.w);
        x[4 * k + 0] = x0; x[4 * k + 1] = x1; x[4 * k + 2] = x2; x[4 * k + 3] = x3;
        mx = fmaxf(mx, fmaxf(fmaxf(x0, x1), fmaxf(x2, x3)));
    }
#pragma unroll
    for (int o = 16; o > 0; o >>= 1)
        mx = fmaxf(mx, __shfl_xor_sync(0xFFFFFFFFu, mx, o));

    __shared__ float rm[4][2], rs[4][2];
    if (lane == 0) rm[rl][half] = mx;
    __syncthreads();
    mx = fmaxf(rm[rl][0], rm[rl][1]);

    float s = 0.0f;
#pragma unroll
    for (int k = 0; k < 16; k++) {
        x[k] = __expf(x[k] - mx);
        s += x[k];
    }
#pragma unroll
    for (int o = 16; o > 0; o >>= 1)
        s += __shfl_xor_sync(0xFFFFFFFFu, s, o);
    if (lane == 0) rs[rl][half] = s;
    __syncthreads();
    float S = rs[rl][0] + rs[rl][1];
    float inv = 1.0f / S;

    uint4 w;
    uint4* __restrict__ q4 = reinterpret_cast<uint4*>(g_q) + r * 128;
    w.x = packbf(x[0] * inv, x[1] * inv);
    w.y = packbf(x[2] * inv, x[3] * inv);
    w.z = packbf(x[4] * inv, x[5] * inv);
    w.w = packbf(x[6] * inv, x[7] * inv);
    q4[tr] = w;
    w.x = packbf(x[8] * inv, x[9] * inv);
    w.y = packbf(x[10] * inv, x[11] * inv);
    w.z = packbf(x[12] * inv, x[13] * inv);
    w.w = packbf(x[14] * inv, x[15] * inv);
    q4[64 + tr] = w;

    if (tr == 0)
        g_u[r] = mx + __logf(S);
}

// ---------------------------------------------------------------------------
// Col pass 1 (r = 1): c_j = 1 / Sum_i K_ij, full column per block tile.
// Tile = 64 bf16 cols x 1024 rows. Block 256 = (8 words x 32 row-groups).
// Grid (16, NB), batches DESCENDING (L2 ping-pong with exp_quant).
// ---------------------------------------------------------------------------
__global__ void __launch_bounds__(256) col1_kernel() {
    int b  = NB - 1 - (int)blockIdx.y;
    int tx = threadIdx.x & 7;
    int ty = threadIdx.x >> 3;      // 0..31
    int c  = blockIdx.x * 8 + tx;

    __shared__ float red[64][33];

    const uint4* __restrict__ q4 = reinterpret_cast<const uint4*>(g_q)
                                   + (size_t)b * N * 128 + c;

    float acc[8] = {0.f, 0.f, 0.f, 0.f, 0.f, 0.f, 0.f, 0.f};
#pragma unroll 8
    for (int k = 0; k < 32; k++) {
        int i = ty + 32 * k;
        uint4 q = q4[(size_t)i * 128];
        acc[0] += blo(q.x); acc[1] += bhi(q.x);
        acc[2] += blo(q.y); acc[3] += bhi(q.y);
        acc[4] += blo(q.z); acc[5] += bhi(q.z);
        acc[6] += blo(q.w); acc[7] += bhi(q.w);
    }
#pragma unroll
    for (int q = 0; q < 8; q++)
        red[tx * 8 + q][ty] = acc[q];
    __syncthreads();

    if (threadIdx.x < 64) {
        int l = threadIdx.x;
        float S = 0.0f;
#pragma unroll
        for (int k = 0; k < 32; k++)
            S += red[l][k];
        S = fmaxf(S, 1e-30f);
        g_c[b * N + blockIdx.x * 64 + l] = 1.0f / S;
    }
}

// ---------------------------------------------------------------------------
// FUSED interior pass: per 32-row panel —
//  phase 1: row dots S_i = Sum_j K_ij c_j  -> r_i = 1/S_i (smem only)
//  phase 2: col partials Sum_{i in panel} K_ij r_i (panel re-read hits L1)
// Block 512 threads, grid 2048 (= NB * NPANEL). dir alternates for L2 reuse.
// ---------------------------------------------------------------------------
__global__ void __launch_bounds__(512) fused_rowcol_kernel(int dir) {
    int wb = dir ? (NB * NPANEL - 1 - (int)blockIdx.x) : (int)blockIdx.x;
    int b = wb >> 5;
    int p = wb & (NPANEL - 1);
    size_t row0 = (size_t)b * N + p * PR;

    __shared__ float rs[8][4][2];
    __shared__ float sr[PR];

    int t = threadIdx.x;
    int rg   = t >> 6;          // 0..7 row-group (4 rows each)
    int tr   = t & 63;
    int half = tr >> 5;
    int lane = t & 31;

    // ---- phase 1: row dots ----
    const float4* __restrict__ c4 = reinterpret_cast<const float4*>(g_c + b * N);
    float4 ca0 = c4[2 * tr];
    float4 cb0 = c4[2 * tr + 1];
    float4 ca1 = c4[128 + 2 * tr];
    float4 cb1 = c4[129 + 2 * tr];

    float sum[4];
#pragma unroll
    for (int rr = 0; rr < 4; rr++) {
        const uint4* __restrict__ q4 = reinterpret_cast<const uint4*>(g_q)
                                       + (row0 + rg * 4 + rr) * 128;
        uint4 qa = q4[tr];
        uint4 qb = q4[64 + tr];
        float s = 0.0f;
        s += blo(qa.x) * ca0.x + bhi(qa.x) * ca0.y;
        s += blo(qa.y) * ca0.z + bhi(qa.y) * ca0.w;
        s += blo(qa.z) * cb0.x + bhi(qa.z) * cb0.y;
        s += blo(qa.w) * cb0.z + bhi(qa.w) * cb0.w;
        s += blo(qb.x) * ca1.x + bhi(qb.x) * ca1.y;
        s += blo(qb.y) * ca1.z + bhi(qb.y) * ca1.w;
        s += blo(qb.z) * cb1.x + bhi(qb.z) * cb1.y;
        s += blo(qb.w) * cb1.z + bhi(qb.w) * cb1.w;
        sum[rr] = s;
    }
#pragma unroll
    for (int rr = 0; rr < 4; rr++) {
#pragma unroll
        for (int o = 16; o > 0; o >>= 1)
            sum[rr] += __shfl_xor_sync(0xFFFFFFFFu, sum[rr], o);
    }
    if (lane == 0) {
#pragma unroll
        for (int rr = 0; rr < 4; rr++)
            rs[rg][rr][half] = sum[rr];
    }
    __syncthreads();

    if (t < PR) {
        int g = t >> 2, rr = t & 3;
        float S = fmaxf(rs[g][rr][0] + rs[g][rr][1], 1e-30f);
        sr[g * 4 + rr] = 1.0f / S;
    }
    __syncthreads();

    // ---- phase 2: column partials over this panel (L1-resident re-read) ----
    const unsigned int* __restrict__ q1 = reinterpret_cast<const unsigned int*>(g_q)
                                          + row0 * 512;
    float a0 = 0.0f, a1 = 0.0f;
#pragma unroll 8
    for (int i = 0; i < PR; i++) {
        unsigned int q = q1[(size_t)i * 512 + t];
        float rr = sr[i];
        a0 += blo(q) * rr;
        a1 += bhi(q) * rr;
    }
    reinterpret_cast<float2*>(g_ps)[((size_t)b * NPANEL + p) * 512 + t] =
        make_float2(a0, a1);
}

// Reduce the NPANEL partials into c_j = 1/S_j.
__global__ void __launch_bounds__(256) reduce_kernel() {
    int t = blockIdx.x * 256 + threadIdx.x;     // 0..NB*N-1
    int b = t >> 10;
    int j = t & (N - 1);

    size_t pb = (size_t)b * NPANEL * N + j;
    float S = 0.0f;
#pragma unroll 8
    for (int p = 0; p < NPANEL; p++)
        S += g_ps[pb + (size_t)p * N];
    S = fmaxf(S, 1e-30f);
    g_c[t] = 1.0f / S;
}

// ---------------------------------------------------------------------------
// Final row pass: u10_i = u1_i + log( Sum_j K_ij c9_j ).
// ---------------------------------------------------------------------------
__global__ void __launch_bounds__(256) row9_kernel() {
    int rg   = threadIdx.x >> 6;
    int tr   = threadIdx.x & 63;
    int half = tr >> 5;
    int lane = threadIdx.x & 31;
    size_t rbase = (size_t)blockIdx.x * 16 + rg * 4;
    int b = (int)(rbase >> 10);

    const float4* __restrict__ c4 = reinterpret_cast<const float4*>(g_c + b * N);
    float4 ca0 = c4[2 * tr];
    float4 cb0 = c4[2 * tr + 1];
    float4 ca1 = c4[128 + 2 * tr];
    float4 cb1 = c4[129 + 2 * tr];

    float sum[4];
#pragma unroll
    for (int rr = 0; rr < 4; rr++) {
        const uint4* __restrict__ q4 = reinterpret_cast<const uint4*>(g_q) + (rbase + rr) * 128;
        uint4 qa = q4[tr];
        uint4 qb = q4[64 + tr];
        float s = 0.0f;
        s += blo(qa.x) * ca0.x + bhi(qa.x) * ca0.y;
        s += blo(qa.y) * ca0.z + bhi(qa.y) * ca0.w;
        s += blo(qa.z) * cb0.x + bhi(qa.z) * cb0.y;
        s += blo(qa.w) * cb0.z + bhi(qa.w) * cb0.w;
        s += blo(qb.x) * ca1.x + bhi(qb.x) * ca1.y;
        s += blo(qb.y) * ca1.z + bhi(qb.y) * ca1.w;
        s += blo(qb.z) * cb1.x + bhi(qb.z) * cb1.y;
        s += blo(qb.w) * cb1.z + bhi(qb.w) * cb1.w;
        sum[rr] = s;
    }
#pragma unroll
    for (int rr = 0; rr < 4; rr++) {
#pragma unroll
        for (int o = 16; o > 0; o >>= 1)
            sum[rr] += __shfl_xor_sync(0xFFFFFFFFu, sum[rr], o);
    }

    __shared__ float rs[4][4][2];
    if (lane == 0) {
#pragma unroll
        for (int rr = 0; rr < 4; rr++)
            rs[rg][rr][half] = sum[rr];
    }
    __syncthreads();

    if (threadIdx.x < 16) {
        int g = threadIdx.x >> 2, rr = threadIdx.x & 3;
        size_t r = (size_t)blockIdx.x * 16 + g * 4 + rr;
        float S = fmaxf(rs[g][rr][0] + rs[g][rr][1], 1e-30f);
        g_u[r] = g_u[r] + __logf(S);
    }
}

// ---------------------------------------------------------------------------
// EXACT last col pass fused with output write (iteration 10 col + exp).
// ---------------------------------------------------------------------------
__global__ void __launch_bounds__(1024) col_lse_finalize_kernel(const float* __restrict__ M,
                                                                float* __restrict__ out) {
    int b  = blockIdx.y;
    int tx = threadIdx.x & 7;
    int ty = threadIdx.x >> 3;
    int lane = threadIdx.x & 31;
    int wid  = threadIdx.x >> 5;
    int j4 = blockIdx.x * 8 + tx;

    __shared__ float us[N];
    __shared__ float4 redm[32][8];
    __shared__ float4 reds[32][8];

    us[threadIdx.x] = g_u[b * N + threadIdx.x];
    __syncthreads();

    const float4* __restrict__ base = reinterpret_cast<const float4*>(M)
                                      + (size_t)b * N * (N / 4) + j4;

    float4 xv[8];
    float4 mx = make_float4(-1e30f, -1e30f, -1e30f, -1e30f);
#pragma unroll
    for (int k = 0; k < 8; k++) {
        int i = ty + 128 * k;
        float4 a = base[(size_t)i * (N / 4)];
        float u = us[i];
        float4 t;
        t.x = clampA(a.x) - u; t.y = clampA(a.y) - u;
        t.z = clampA(a.z) - u; t.w = clampA(a.w) - u;
        xv[k] = t;
        mx.x = fmaxf(mx.x, t.x); mx.y = fmaxf(mx.y, t.y);
        mx.z = fmaxf(mx.z, t.z); mx.w = fmaxf(mx.w, t.w);
    }

#pragma unroll
    for (int o = 8; o <= 16; o <<= 1) {
        mx.x = fmaxf(mx.x, __shfl_xor_sync(0xFFFFFFFFu, mx.x, o));
        mx.y = fmaxf(mx.y, __shfl_xor_sync(0xFFFFFFFFu, mx.y, o));
        mx.z = fmaxf(mx.z, __shfl_xor_sync(0xFFFFFFFFu, mx.z, o));
        mx.w = fmaxf(mx.w, __shfl_xor_sync(0xFFFFFFFFu, mx.w, o));
    }
    if (lane < 8) redm[wid][lane] = mx;
    __syncthreads();
#pragma unroll
    for (int h = 16; h > 0; h >>= 1) {
        if (threadIdx.x < (unsigned)(h * 8)) {
            int w = threadIdx.x >> 3, x = threadIdx.x & 7;
            float4 a = redm[w][x], c = redm[w + h][x];
            a.x = fmaxf(a.x, c.x); a.y = fmaxf(a.y, c.y);
            a.z = fmaxf(a.z, c.z); a.w = fmaxf(a.w, c.w);
            redm[w][x] = a;
        }
        __syncthreads();
    }
    float4 MX = redm[0][tx];

    float4 s = make_float4(0.f, 0.f, 0.f, 0.f);
#pragma unroll
    for (int k = 0; k < 8; k++) {
        s.x += __expf(xv[k].x - MX.x);
        s.y += __expf(xv[k].y - MX.y);
        s.z += __expf(xv[k].z - MX.z);
        s.w += __expf(xv[k].w - MX.w);
    }
#pragma unroll
    for (int o = 8; o <= 16; o <<= 1) {
        s.x += __shfl_xor_sync(0xFFFFFFFFu, s.x, o);
        s.y += __shfl_xor_sync(0xFFFFFFFFu, s.y, o);
        s.z += __shfl_xor_sync(0xFFFFFFFFu, s.z, o);
        s.w += __shfl_xor_sync(0xFFFFFFFFu, s.w, o);
    }
    if (lane < 8) reds[wid][lane] = s;
    __syncthreads();
#pragma unroll
    for (int h = 16; h > 0; h >>= 1) {
        if (threadIdx.x < (unsigned)(h * 8)) {
            int w = threadIdx.x >> 3, x = threadIdx.x & 7;
            float4 a = reds[w][x], c = reds[w + h][x];
            a.x += c.x; a.y += c.y; a.z += c.z; a.w += c.w;
            reds[w][x] = a;
        }
        __syncthreads();
    }
    float4 SS = reds[0][tx];

    float4 V;
    V.x = MX.x + __logf(SS.x);
    V.y = MX.y + __logf(SS.y);
    V.z = MX.z + __logf(SS.z);
    V.w = MX.w + __logf(SS.w);

    float4* __restrict__ obase = reinterpret_cast<float4*>(out)
                                 + (size_t)b * N * (N / 4) + j4;
#pragma unroll
    for (int k = 0; k < 8; k++) {
        int i = ty + 128 * k;
        float4 o;
        o.x = __expf(xv[k].x - V.x);
        o.y = __expf(xv[k].y - V.y);
        o.z = __expf(xv[k].z - V.z);
        o.w = __expf(xv[k].w - V.w);
        obase[(size_t)i * (N / 4)] = o;
    }
}

extern "C" void kernel_launch(void* const* d_in, const int* in_sizes, int n_in,
                              void* d_out, int out_size) {
    const float* M = (const float*)d_in[0];
    float* out = (float*)d_out;

    // u1 + K (bf16)
    exp_quant_kernel<<<(NB * N) / 4, 256>>>(M);
    // c1 = 1 / colsum(K)
    col1_kernel<<<dim3(16, NB), 256>>>();

    // 8 fused iterations: row(it) + col partials -> reduce -> c(it+1)
    for (int it = 0; it < 8; it++) {
        fused_rowcol_kernel<<<NB * NPANEL, 512>>>(it & 1);
        reduce_kernel<<<(NB * N) / 256, 256>>>();
    }

    // u10 = u1 + log(K c9)
    row9_kernel<<<(NB * N) / 16, 256>>>();
    // exact final col pass + exp output
    col_lse_finalize_kernel<<<dim3(N / 32, NB), 1024>>>(M, out);
}

// round 14
// speedup vs baseline: 1.5399x; 1.0104x over previous
#include <cuda_runtime.h>
#include <cuda_bf16.h>
#include <math.h>

#define NB 64
#define N 1024
#define NPANEL 16              // row panels per batch
#define PR 64                  // rows per panel

// Scratch (allocation-free, static device memory)
__device__ __align__(16) float g_u[NB * N];                 // u1, later u10
__device__ __align__(16) float g_c[NB * N];                 // exp-domain col scaling
__device__ __align__(16) float g_ps[NB * NPANEL * N];       // col partials (4 MB)
// K = exp(A - u1) stored as bf16
__device__ __align__(16) unsigned short g_q[(size_t)NB * N * N];

__device__ __forceinline__ float clampA(float m) {
    return fminf(fmaxf(m, -25.0f), 25.0f) * 10.0f;
}
__device__ __forceinline__ float blo(unsigned int w) { return __uint_as_float(w << 16); }
__device__ __forceinline__ float bhi(unsigned int w) { return __uint_as_float(w & 0xFFFF0000u); }
__device__ __forceinline__ unsigned int packbf(float lo, float hi) {
    __nv_bfloat162 h = __floats2bfloat162_rn(lo, hi);
    return *reinterpret_cast<unsigned int*>(&h);
}

// ---------------------------------------------------------------------------
// Pass 0: exact row-LSE (u1) + K = exp(A - u1) in bf16.
// ---------------------------------------------------------------------------
__global__ void __launch_bounds__(256, 2) exp_quant_kernel(const float* __restrict__ M) {
    int rl   = threadIdx.x >> 6;
    int tr   = threadIdx.x & 63;
    int half = tr >> 5;
    int lane = tr & 31;
    size_t r = (size_t)blockIdx.x * 4 + rl;

    const float4* __restrict__ row4 = reinterpret_cast<const float4*>(M) + r * (N / 4);

    float x[16];
    float mx = -1e30f;
#pragma unroll
    for (int k = 0; k < 4; k++) {
        int idx = (k & 1) + 2 * tr + (k >> 1) * 128;
        float4 a = row4[idx];
        float x0 = clampA(a.x), x1 = clampA(a.y), x2 = clampA(a.z), x3 = clampA(a.w);
        x[4 * k + 0] = x0; x[4 * k + 1] = x1; x[4 * k + 2] = x2; x[4 * k + 3] = x3;
        mx = fmaxf(mx, fmaxf(fmaxf(x0, x1), fmaxf(x2, x3)));
    }
#pragma unroll
    for (int o = 16; o > 0; o >>= 1)
        mx = fmaxf(mx, __shfl_xor_sync(0xFFFFFFFFu, mx, o));

    __shared__ float rm[4][2], rs[4][2];
    if (lane == 0) rm[rl][half] = mx;
    __syncthreads();
    mx = fmaxf(rm[rl][0], rm[rl][1]);

    float s = 0.0f;
#pragma unroll
    for (int k = 0; k < 16; k++) {
        x[k] = __expf(x[k] - mx);
        s += x[k];
    }
#pragma unroll
    for (int o = 16; o > 0; o >>= 1)
        s += __shfl_xor_sync(0xFFFFFFFFu, s, o);
    if (lane == 0) rs[rl][half] = s;
    __syncthreads();
    float S = rs[rl][0] + rs[rl][1];
    float inv = 1.0f / S;

    uint4 w;
    uint4* __restrict__ q4 = reinterpret_cast<uint4*>(g_q) + r * 128;
    w.x = packbf(x[0] * inv, x[1] * inv);
    w.y = packbf(x[2] * inv, x[3] * inv);
    w.z = packbf(x[4] * inv, x[5] * inv);
    w.w = packbf(x[6] * inv, x[7] * inv);
    q4[tr] = w;
    w.x = packbf(x[8] * inv, x[9] * inv);
    w.y = packbf(x[10] * inv, x[11] * inv);
    w.z = packbf(x[12] * inv, x[13] * inv);
    w.w = packbf(x[14] * inv, x[15] * inv);
    q4[64 + tr] = w;

    if (tr == 0)
        g_u[r] = mx + __logf(S);
}

// ---------------------------------------------------------------------------
// Col pass 1 (r = 1): c_j = 1 / Sum_i K_ij, full column per block tile.
// Tile = 64 bf16 cols x 1024 rows. Block 256, grid (16, NB), batches DESC.
// ---------------------------------------------------------------------------
__global__ void __launch_bounds__(256) col1_kernel() {
    int b  = NB - 1 - (int)blockIdx.y;
    int tx = threadIdx.x & 7;
    int ty = threadIdx.x >> 3;      // 0..31
    int c  = blockIdx.x * 8 + tx;

    __shared__ float red[64][33];

    const uint4* __restrict__ q4 = reinterpret_cast<const uint4*>(g_q)
                                   + (size_t)b * N * 128 + c;

    float acc[8] = {0.f, 0.f, 0.f, 0.f, 0.f, 0.f, 0.f, 0.f};
#pragma unroll 8
    for (int k = 0; k < 32; k++) {
        int i = ty + 32 * k;
        uint4 q = q4[(size_t)i * 128];
        acc[0] += blo(q.x); acc[1] += bhi(q.x);
        acc[2] += blo(q.y); acc[3] += bhi(q.y);
        acc[4] += blo(q.z); acc[5] += bhi(q.z);
        acc[6] += blo(q.w); acc[7] += bhi(q.w);
    }
#pragma unroll
    for (int q = 0; q < 8; q++)
        red[tx * 8 + q][ty] = acc[q];
    __syncthreads();

    if (threadIdx.x < 64) {
        int l = threadIdx.x;
        float S = 0.0f;
#pragma unroll
        for (int k = 0; k < 32; k++)
            S += red[l][k];
        S = fmaxf(S, 1e-30f);
        g_c[b * N + blockIdx.x * 64 + l] = 1.0f / S;
    }
}

// ---------------------------------------------------------------------------
// FUSED interior pass, 64-row panels, with inline c-prologue:
//  phase 0: c = 1/(sum of 16 panel partials) into smem (or g_c if first)
//  phase 1: row dots S_i = Sum_j K_ij c_j -> r_i = 1/S_i (smem only)
//  phase 2: col partials Sum_{i in panel} K_ij r_i -> g_ps (panel re-read L1/L2)
// Block 512, grid NB*NPANEL = 1024. dir alternates for L2 reuse.
// ---------------------------------------------------------------------------
__global__ void __launch_bounds__(512) fused_rowcol_kernel(int dir, int first) {
    int wb = dir ? (NB * NPANEL - 1 - (int)blockIdx.x) : (int)blockIdx.x;
    int b = wb >> 4;
    int p = wb & (NPANEL - 1);
    size_t row0 = (size_t)b * N + p * PR;

    __shared__ float sc[N];         // c for this batch
    __shared__ float sr[PR];        // r for this panel
    __shared__ float rs[8][8][2];

    int t = threadIdx.x;

    // ---- phase 0: column scalings ----
    if (first) {
        sc[t]       = g_c[b * N + t];
        sc[t + 512] = g_c[b * N + t + 512];
    } else {
        const float2* __restrict__ ps2 = reinterpret_cast<const float2*>(g_ps);
        float2 S = make_float2(0.f, 0.f);
#pragma unroll
        for (int pp = 0; pp < NPANEL; pp++) {
            float2 q = ps2[((size_t)(b * NPANEL + pp)) * 512 + t];
            S.x += q.x; S.y += q.y;
        }
        sc[2 * t]     = 1.0f / fmaxf(S.x, 1e-30f);
        sc[2 * t + 1] = 1.0f / fmaxf(S.y, 1e-30f);
    }
    __syncthreads();

    // ---- phase 1: row dots ----
    int rg   = t >> 6;          // 0..7 row-group (8 rows each)
    int tr   = t & 63;
    int half = tr >> 5;
    int lane = t & 31;

    float4 ca0 = *reinterpret_cast<const float4*>(&sc[8 * tr]);
    float4 cb0 = *reinterpret_cast<const float4*>(&sc[8 * tr + 4]);
    float4 ca1 = *reinterpret_cast<const float4*>(&sc[512 + 8 * tr]);
    float4 cb1 = *reinterpret_cast<const float4*>(&sc[512 + 8 * tr + 4]);

    float sums[8];
#pragma unroll
    for (int rr = 0; rr < 8; rr++) {
        const uint4* __restrict__ q4 = reinterpret_cast<const uint4*>(g_q)
                                       + (row0 + rg * 8 + rr) * 128;
        uint4 qa = q4[tr];
        uint4 qb = q4[64 + tr];
        float s = 0.0f;
        s += blo(qa.x) * ca0.x + bhi(qa.x) * ca0.y;
        s += blo(qa.y) * ca0.z + bhi(qa.y) * ca0.w;
        s += blo(qa.z) * cb0.x + bhi(qa.z) * cb0.y;
        s += blo(qa.w) * cb0.z + bhi(qa.w) * cb0.w;
        s += blo(qb.x) * ca1.x + bhi(qb.x) * ca1.y;
        s += blo(qb.y) * ca1.z + bhi(qb.y) * ca1.w;
        s += blo(qb.z) * cb1.x + bhi(qb.z) * cb1.y;
        s += blo(qb.w) * cb1.z + bhi(qb.w) * cb1.w;
        sums[rr] = s;
    }
#pragma unroll
    for (int rr = 0; rr < 8; rr++) {
#pragma unroll
        for (int o = 16; o > 0; o >>= 1)
            sums[rr] += __shfl_xor_sync(0xFFFFFFFFu, sums[rr], o);
    }
    if (lane == 0) {
#pragma unroll
        for (int rr = 0; rr < 8; rr++)
            rs[rg][rr][half] = sums[rr];
    }
    __syncthreads();

    if (t < PR) {
        int g = t >> 3, rr = t & 7;     // row within panel = g*8+rr = t
        float S = fmaxf(rs[g][rr][0] + rs[g][rr][1], 1e-30f);
        sr[t] = 1.0f / S;
    }
    __syncthreads();

    // ---- phase 2: column partials over this panel (recent re-read, L1/L2) ----
    const unsigned int* __restrict__ q1 = reinterpret_cast<const unsigned int*>(g_q)
                                          + row0 * 512;
    float a0 = 0.0f, a1 = 0.0f;
#pragma unroll 8
    for (int i = 0; i < PR; i++) {
        unsigned int q = q1[(size_t)i * 512 + t];
        float rr = sr[i];
        a0 += blo(q) * rr;
        a1 += bhi(q) * rr;
    }
    reinterpret_cast<float2*>(g_ps)[((size_t)(b * NPANEL + p)) * 512 + t] =
        make_float2(a0, a1);
}

// Final reduce (one launch): c9_j = 1/S_j from the last fused partials.
__global__ void __launch_bounds__(256) reduce_kernel() {
    int t = blockIdx.x * 256 + threadIdx.x;     // float2 units, 0..NB*512-1
    int b = t >> 9;
    int w = t & 511;

    const float2* __restrict__ ps2 = reinterpret_cast<const float2*>(g_ps);
    float2 S = make_float2(0.f, 0.f);
#pragma unroll
    for (int pp = 0; pp < NPANEL; pp++) {
        float2 q = ps2[((size_t)(b * NPANEL + pp)) * 512 + w];
        S.x += q.x; S.y += q.y;
    }
    float2 c;
    c.x = 1.0f / fmaxf(S.x, 1e-30f);
    c.y = 1.0f / fmaxf(S.y, 1e-30f);
    reinterpret_cast<float2*>(g_c)[b * 512 + w] = c;
}

// ---------------------------------------------------------------------------
// Final row pass: u10_i = u1_i + log( Sum_j K_ij c9_j ).
// ---------------------------------------------------------------------------
__global__ void __launch_bounds__(256) row9_kernel() {
    int rg   = threadIdx.x >> 6;
    int tr   = threadIdx.x & 63;
    int half = tr >> 5;
    int lane = threadIdx.x & 31;
    size_t rbase = (size_t)blockIdx.x * 16 + rg * 4;
    int b = (int)(rbase >> 10);

    const float4* __restrict__ c4 = reinterpret_cast<const float4*>(g_c + b * N);
    float4 ca0 = c4[2 * tr];
    float4 cb0 = c4[2 * tr + 1];
    float4 ca1 = c4[128 + 2 * tr];
    float4 cb1 = c4[129 + 2 * tr];

    float sum[4];
#pragma unroll
    for (int rr = 0; rr < 4; rr++) {
        const uint4* __restrict__ q4 = reinterpret_cast<const uint4*>(g_q) + (rbase + rr) * 128;
        uint4 qa = q4[tr];
        uint4 qb = q4[64 + tr];
        float s = 0.0f;
        s += blo(qa.x) * ca0.x + bhi(qa.x) * ca0.y;
        s += blo(qa.y) * ca0.z + bhi(qa.y) * ca0.w;
        s += blo(qa.z) * cb0.x + bhi(qa.z) * cb0.y;
        s += blo(qa.w) * cb0.z + bhi(qa.w) * cb0.w;
        s += blo(qb.x) * ca1.x + bhi(qb.x) * ca1.y;
        s += blo(qb.y) * ca1.z + bhi(qb.y) * ca1.w;
        s += blo(qb.z) * cb1.x + bhi(qb.z) * cb1.y;
        s += blo(qb.w) * cb1.z + bhi(qb.w) * cb1.w;
        sum[rr] = s;
    }
#pragma unroll
    for (int rr = 0; rr < 4; rr++) {
#pragma unroll
        for (int o = 16; o > 0; o >>= 1)
            sum[rr] += __shfl_xor_sync(0xFFFFFFFFu, sum[rr], o);
    }

    __shared__ float rs[4][4][2];
    if (lane == 0) {
#pragma unroll
        for (int rr = 0; rr < 4; rr++)
            rs[rg][rr][half] = sum[rr];
    }
    __syncthreads();

    if (threadIdx.x < 16) {
        int g = threadIdx.x >> 2, rr = threadIdx.x & 3;
        size_t r = (size_t)blockIdx.x * 16 + g * 4 + rr;
        float S = fmaxf(rs[g][rr][0] + rs[g][rr][1], 1e-30f);
        g_u[r] = g_u[r] + __logf(S);
    }
}

// ---------------------------------------------------------------------------
// EXACT last col pass fused with output write (iteration 10 col + exp).
// ---------------------------------------------------------------------------
__global__ void __launch_bounds__(1024) col_lse_finalize_kernel(const float* __restrict__ M,
                                                                float* __restrict__ out) {
    int b  = blockIdx.y;
    int tx = threadIdx.x & 7;
    int ty = threadIdx.x >> 3;
    int lane = threadIdx.x & 31;
    int wid  = threadIdx.x >> 5;
    int j4 = blockIdx.x * 8 + tx;

    __shared__ float us[N];
    __shared__ float4 redm[32][8];
    __shared__ float4 reds[32][8];

    us[threadIdx.x] = g_u[b * N + threadIdx.x];
    __syncthreads();

    const float4* __restrict__ base = reinterpret_cast<const float4*>(M)
                                      + (size_t)b * N * (N / 4) + j4;

    float4 xv[8];
    float4 mx = make_float4(-1e30f, -1e30f, -1e30f, -1e30f);
#pragma unroll
    for (int k = 0; k < 8; k++) {
        int i = ty + 128 * k;
        float4 a = base[(size_t)i * (N / 4)];
        float u = us[i];
        float4 t;
        t.x = clampA(a.x) - u; t.y = clampA(a.y) - u;
        t.z = clampA(a.z) - u; t.w = clampA(a.w) - u;
        xv[k] = t;
        mx.x = fmaxf(mx.x, t.x); mx.y = fmaxf(mx.y, t.y);
        mx.z = fmaxf(mx.z, t.z); mx.w = fmaxf(mx.w, t.w);
    }

#pragma unroll
    for (int o = 8; o <= 16; o <<= 1) {
        mx.x = fmaxf(mx.x, __shfl_xor_sync(0xFFFFFFFFu, mx.x, o));
        mx.y = fmaxf(mx.y, __shfl_xor_sync(0xFFFFFFFFu, mx.y, o));
        mx.z = fmaxf(mx.z, __shfl_xor_sync(0xFFFFFFFFu, mx.z, o));
        mx.w = fmaxf(mx.w, __shfl_xor_sync(0xFFFFFFFFu, mx.w, o));
    }
    if (lane < 8) redm[wid][lane] = mx;
    __syncthreads();
#pragma unroll
    for (int h = 16; h > 0; h >>= 1) {
        if (threadIdx.x < (unsigned)(h * 8)) {
            int w = threadIdx.x >> 3, x = threadIdx.x & 7;
            float4 a = redm[w][x], c = redm[w + h][x];
            a.x = fmaxf(a.x, c.x); a.y = fmaxf(a.y, c.y);
            a.z = fmaxf(a.z, c.z); a.w = fmaxf(a.w, c.w);
            redm[w][x] = a;
        }
        __syncthreads();
    }
    float4 MX = redm[0][tx];

    float4 s = make_float4(0.f, 0.f, 0.f, 0.f);
#pragma unroll
    for (int k = 0; k < 8; k++) {
        s.x += __expf(xv[k].x - MX.x);
        s.y += __expf(xv[k].y - MX.y);
        s.z += __expf(xv[k].z - MX.z);
        s.w += __expf(xv[k].w - MX.w);
    }
#pragma unroll
    for (int o = 8; o <= 16; o <<= 1) {
        s.x += __shfl_xor_sync(0xFFFFFFFFu, s.x, o);
        s.y += __shfl_xor_sync(0xFFFFFFFFu, s.y, o);
        s.z += __shfl_xor_sync(0xFFFFFFFFu, s.z, o);
        s.w += __shfl_xor_sync(0xFFFFFFFFu, s.w, o);
    }
    if (lane < 8) reds[wid][lane] = s;
    __syncthreads();
#pragma unroll
    for (int h = 16; h > 0; h >>= 1) {
        if (threadIdx.x < (unsigned)(h * 8)) {
            int w = threadIdx.x >> 3, x = threadIdx.x & 7;
            float4 a = reds[w][x], c = reds[w + h][x];
            a.x += c.x; a.y += c.y; a.z += c.z; a.w += c.w;
            reds[w][x] = a;
        }
        __syncthreads();
    }
    float4 SS = reds[0][tx];

    float4 V;
    V.x = MX.x + __logf(SS.x);
    V.y = MX.y + __logf(SS.y);
    V.z = MX.z + __logf(SS.z);
    V.w = MX.w + __logf(SS.w);

    float4* __restrict__ obase = reinterpret_cast<float4*>(out)
                                 + (size_t)b * N * (N / 4) + j4;
#pragma unroll
    for (int k = 0; k < 8; k++) {
        int i = ty + 128 * k;
        float4 o;
        o.x = __expf(xv[k].x - V.x);
        o.y = __expf(xv[k].y - V.y);
        o.z = __expf(xv[k].z - V.z);
        o.w = __expf(xv[k].w - V.w);
        obase[(size_t)i * (N / 4)] = o;
    }
}

extern "C" void kernel_launch(void* const* d_in, const int* in_sizes, int n_in,
                              void* d_out, int out_size) {
    const float* M = (const float*)d_in[0];
    float* out = (float*)d_out;

    // u1 + K (bf16)
    exp_quant_kernel<<<(NB * N) / 4, 256>>>(M);
    // c1 = 1 / colsum(K)
    col1_kernel<<<dim3(16, NB), 256>>>();

    // 8 fused iterations, c-reduction inlined in the prologue of the next one
    for (int it = 0; it < 8; it++) {
        fused_rowcol_kernel<<<NB * NPANEL, 512>>>(it & 1, it == 0 ? 1 : 0);
    }

    // c9 from last partials, then u10 = u1 + log(K c9)
    reduce_kernel<<<(NB * 512) / 256, 256>>>();
    row9_kernel<<<(NB * N) / 16, 256>>>();
    // exact final col pass + exp output
    col_lse_finalize_kernel<<<dim3(N / 32, NB), 1024>>>(M, out);
}